// round 5
// baseline (speedup 1.0000x reference)
#include <cuda_runtime.h>
#include <math.h>

#define B 32
#define N 32768
#define D 128
#define CH 128
#define NCH (N / CH)          // 256 chunks
#define YSTRIDE (D + 4)       // 132 floats (528B rows, 16B aligned): no LDS conflicts

typedef unsigned long long u64;

// per-chunk softmax partials (no allocations allowed)
__device__ float g_cmax[B * NCH];        // [B][NCH]
__device__ float g_csum[B * NCH];        // [B][NCH]
__device__ float g_cvec[B * D * NCH];    // [B][D][NCH], 4 MB (chunk-major for coalesced reduce)

__device__ __forceinline__ u64 fma2(u64 a, u64 b, u64 c) {
    u64 d;
    asm("fma.rn.f32x2 %0, %1, %2, %3;" : "=l"(d) : "l"(a), "l"(b), "l"(c));
    return d;
}
__device__ __forceinline__ u64 pk(float lo, float hi) {
    u64 r;
    asm("mov.b64 %0, {%1, %2};" : "=l"(r) : "f"(lo), "f"(hi));
    return r;
}
__device__ __forceinline__ float hsum2(u64 v) {
    float lo, hi;
    asm("mov.b64 {%0, %1}, %2;" : "=f"(lo), "=f"(hi) : "l"(v));
    return lo + hi;
}

// ---------------------------------------------------------------------------
// K1: fused chunk kernel, FFMA2 throughout. One CTA per 128-n chunk.
// ---------------------------------------------------------------------------
__global__ __launch_bounds__(128, 2) void k_chunk(const float* __restrict__ x,
                                                  const float* __restrict__ al,
                                                  const float* __restrict__ y) {
    extern __shared__ float smem[];
    float* ys = smem;                    // CH * YSTRIDE   (67.6 KB)
    float* xs = ys + CH * YSTRIDE;       // B * D          (16 KB)
    float* es = xs + B * D;              // B * CH         (16 KB)
    __shared__ float sA[B], sScale[B], sC[B], cm[B];
    __shared__ float wred[B][4];

    const int t = threadIdx.x;
    const int base = blockIdx.x * CH;

    // stage y chunk (coalesced float4, padded rows)
    const float4* y4 = reinterpret_cast<const float4*>(y + (size_t)base * D);
    #pragma unroll
    for (int i = t; i < CH * D / 4; i += 128) {
        int row = i >> 5;
        int c4  = i & 31;
        *reinterpret_cast<float4*>(&ys[row * YSTRIDE + c4 * 4]) = y4[i];
    }
    const float4* x4 = reinterpret_cast<const float4*>(x);
    #pragma unroll
    for (int i = t; i < B * D / 4; i += 128)
        reinterpret_cast<float4*>(xs)[i] = x4[i];
    __syncthreads();

    if (t < B) {
        float a = al[t];
        float var = 1.0f - a;
        float x2 = 0.f;
        #pragma unroll 8
        for (int d = 0; d < D; d++) { float v = xs[t * D + d]; x2 = fmaf(v, v, x2); }
        sA[t] = -(0.5f * (float)D * logf(var) + 0.5f / var * x2);
        sScale[t] = sqrtf(a) / var;
        sC[t] = 0.5f * a / var;
    }
    __syncthreads();

    // ---- Phase A: dots via f32x2, pairing adjacent d ----
    u64 dot2[B];
    #pragma unroll
    for (int b = 0; b < B; b++) dot2[b] = 0ull;
    u64 y2a = 0ull, y2b = 0ull;

    const ulonglong2* yrow2 = reinterpret_cast<const ulonglong2*>(&ys[t * YSTRIDE]);
    const ulonglong2* xs2   = reinterpret_cast<const ulonglong2*>(xs);
    #pragma unroll 4
    for (int d4 = 0; d4 < D / 4; d4++) {
        ulonglong2 yv = yrow2[d4];       // (y[d],y[d+1]) , (y[d+2],y[d+3])
        y2a = fma2(yv.x, yv.x, y2a);
        y2b = fma2(yv.y, yv.y, y2b);
        #pragma unroll
        for (int b = 0; b < B; b++) {
            ulonglong2 xv = xs2[b * (D / 4) + d4];   // broadcast
            dot2[b] = fma2(xv.x, yv.x, dot2[b]);
            dot2[b] = fma2(xv.y, yv.y, dot2[b]);
        }
    }
    const float y2 = hsum2(y2a) + hsum2(y2b);

    const int lane = t & 31, w = t >> 5;
    #pragma unroll
    for (int b = 0; b < B; b++) {
        float l = fmaf(sScale[b], hsum2(dot2[b]), sA[b]) - sC[b] * y2;
        es[b * CH + t] = l;
        float m = l;
        #pragma unroll
        for (int o = 16; o > 0; o >>= 1) m = fmaxf(m, __shfl_xor_sync(0xffffffffu, m, o));
        if (lane == 0) wred[b][w] = m;
    }
    __syncthreads();
    if (t < B) {
        float m = fmaxf(fmaxf(wred[t][0], wred[t][1]), fmaxf(wred[t][2], wred[t][3]));
        cm[t] = m;
        g_cmax[t * NCH + blockIdx.x] = m;
    }
    __syncthreads();

    #pragma unroll
    for (int b = 0; b < B; b++)
        es[b * CH + t] = __expf(es[b * CH + t] - cm[b]);
    __syncthreads();

    #pragma unroll
    for (int j = 0; j < B / 4; j++) {
        int b = w * (B / 4) + j;
        float s = es[b * CH + lane] + es[b * CH + lane + 32]
                + es[b * CH + lane + 64] + es[b * CH + lane + 96];
        #pragma unroll
        for (int o = 16; o > 0; o >>= 1) s += __shfl_xor_sync(0xffffffffu, s, o);
        if (lane == 0) g_csum[b * NCH + blockIdx.x] = s;
    }

    // ---- Phase B: acc[b][d=t] = sum_n e[b][n]*y[n][d], f32x2 pairing adjacent n ----
    u64 acc2[B];
    #pragma unroll
    for (int b = 0; b < B; b++) acc2[b] = 0ull;

    #pragma unroll 2
    for (int n4 = 0; n4 < CH / 4; n4++) {
        const int n = n4 * 4;
        u64 yp0 = pk(ys[(n + 0) * YSTRIDE + t], ys[(n + 1) * YSTRIDE + t]);
        u64 yp1 = pk(ys[(n + 2) * YSTRIDE + t], ys[(n + 3) * YSTRIDE + t]);
        #pragma unroll
        for (int b = 0; b < B; b++) {
            ulonglong2 e2 = *reinterpret_cast<const ulonglong2*>(&es[b * CH + n]); // broadcast
            acc2[b] = fma2(e2.x, yp0, acc2[b]);
            acc2[b] = fma2(e2.y, yp1, acc2[b]);
        }
    }

    // store transposed: [b][d][c]
    #pragma unroll
    for (int b = 0; b < B; b++)
        g_cvec[((size_t)b * D + t) * NCH + blockIdx.x] = hsum2(acc2[b]);
}

// ---------------------------------------------------------------------------
// K2: finisher. Grid = B * (D/4) = 1024 CTAs, 128 threads.
//  CTA (b,g): block-parallel M_b, SE_b from chunk partials; warp w owns
//  d = 4g + w; lanes stride chunks (coalesced in [b][d][c] layout).
// ---------------------------------------------------------------------------
__global__ __launch_bounds__(128) void k_final(const float* __restrict__ x,
                                               const float* __restrict__ al,
                                               float* __restrict__ out) {
    __shared__ float sc[NCH];
    __shared__ float red[4];
    __shared__ float sM, sSE;
    const int t = threadIdx.x, lane = t & 31, w = t >> 5;
    const int b = blockIdx.x >> 5;
    const int g = blockIdx.x & 31;

    float c0 = g_cmax[b * NCH + t];
    float c1 = g_cmax[b * NCH + t + 128];
    float m = fmaxf(c0, c1);
    #pragma unroll
    for (int o = 16; o > 0; o >>= 1) m = fmaxf(m, __shfl_xor_sync(0xffffffffu, m, o));
    if (lane == 0) red[w] = m;
    __syncthreads();
    if (t == 0) sM = fmaxf(fmaxf(red[0], red[1]), fmaxf(red[2], red[3]));
    __syncthreads();
    const float M = sM;

    float s0 = __expf(c0 - M);
    float s1 = __expf(c1 - M);
    sc[t] = s0;
    sc[t + 128] = s1;
    float ps = fmaf(s0, g_csum[b * NCH + t], s1 * g_csum[b * NCH + t + 128]);
    #pragma unroll
    for (int o = 16; o > 0; o >>= 1) ps += __shfl_xor_sync(0xffffffffu, ps, o);
    if (lane == 0) red[w] = ps;
    __syncthreads();
    if (t == 0) sSE = red[0] + red[1] + red[2] + red[3];
    __syncthreads();

    const int d = g * 4 + w;
    const float* pv = g_cvec + ((size_t)b * D + d) * NCH;
    float v = 0.f;
    #pragma unroll
    for (int j = 0; j < NCH / 32; j++) {
        const int c = j * 32 + lane;       // coalesced 128B line per j
        v = fmaf(sc[c], pv[c], v);
    }
    #pragma unroll
    for (int o = 16; o > 0; o >>= 1) v += __shfl_xor_sync(0xffffffffu, v, o);

    if (lane == 0) {
        float a = al[b];
        float var = 1.f - a;
        out[b * D + d] = (x[b * D + d] - sqrtf(a) * (v / sSE)) * rsqrtf(var);
    }
}

extern "C" void kernel_launch(void* const* d_in, const int* in_sizes, int n_in,
                              void* d_out, int out_size) {
    const float* x  = (const float*)d_in[0];   // inputs [B, D]
    const float* al = (const float*)d_in[1];   // alphas [B]
    const float* y  = (const float*)d_in[2];   // data_batch [N, D]
    float* out = (float*)d_out;                // [B, D]

    const size_t SMEM = (CH * YSTRIDE + B * D + B * CH) * sizeof(float);  // ~98 KB
    cudaFuncSetAttribute(k_chunk, cudaFuncAttributeMaxDynamicSharedMemorySize, (int)SMEM);

    k_chunk<<<NCH, 128, SMEM>>>(x, al, y);
    k_final<<<B * (D / 4), 128>>>(x, al, out);
}